// round 9
// baseline (speedup 1.0000x reference)
#include <cuda_runtime.h>
#include <cuda_fp16.h>
#include <cuda_fp8.h>
#include <math.h>

// Problem constants (fixed by the reference)
#define NROWS 25088     // B*H*W
#define DIM   64
#define KNEG  100
#define HW    3136      // H*W
#define DHW   200704    // D*H*W

// Scratch (no cudaMalloc allowed)
__device__ unsigned char g_x1q[NROWS * DIM];   // normalized x1, fp8 e4m3, 1.6MB
__device__ float         g_pos[NROWS];
__device__ float         g_loss[NROWS];

// ---------------------------------------------------------------------------
// Kernel A (round-4 proven): Block = 256 threads = 8 warps handles 32 rows.
// Warp w owns dims [8w, 8w+8) for all 32 rows; lane = row-within-block.
// Every global load is one 128B warp transaction. Cross-warp reductions via
// smem. 32 | 3136 so a block never straddles a batch boundary.
// ---------------------------------------------------------------------------
__global__ void normalize_kernel(const float* __restrict__ x1,
                                 const float* __restrict__ x2) {
    __shared__ float s1s[8][32];
    __shared__ float s2s[8][32];
    __shared__ float pss[8][32];

    int lane = threadIdx.x & 31;   // row within block
    int part = threadIdx.x >> 5;   // dim chunk (warp id)
    int n = blockIdx.x * 32 + lane;
    int b  = n / HW;
    int hw = n - b * HW;
    const float* p1 = x1 + (size_t)b * DHW + (size_t)(part * 8) * HW + hw;
    const float* p2 = x2 + (size_t)b * DHW + (size_t)(part * 8) * HW + hw;

    float v1[8], v2[8];
    #pragma unroll
    for (int i = 0; i < 8; i++) v1[i] = p1[i * HW];
    #pragma unroll
    for (int i = 0; i < 8; i++) v2[i] = p2[i * HW];

    float s1 = 0.f, s2 = 0.f;
    #pragma unroll
    for (int i = 0; i < 8; i++) {
        s1 = fmaf(v1[i], v1[i], s1);
        s2 = fmaf(v2[i], v2[i], s2);
    }
    s1s[part][lane] = s1;
    s2s[part][lane] = s2;
    __syncthreads();

    float t1 = 0.f, t2 = 0.f;
    #pragma unroll
    for (int p = 0; p < 8; p++) { t1 += s1s[p][lane]; t2 += s2s[p][lane]; }
    float sc1 = 1.0f / fmaxf(sqrtf(t1), 1e-12f);
    float sc2 = 1.0f / fmaxf(sqrtf(t2), 1e-12f);

    float pos = 0.f;
    __nv_fp8x2_storage_t qv[4];
    #pragma unroll
    for (int i = 0; i < 4; i++) {
        float a0 = v1[2*i]   * sc1;
        float a1 = v1[2*i+1] * sc1;
        pos += __expf(a0 * (v2[2*i]   * sc2));
        pos += __expf(a1 * (v2[2*i+1] * sc2));
        float2 f2; f2.x = a0; f2.y = a1;
        qv[i] = __nv_cvt_float2_to_fp8x2(f2, __NV_SATFINITE, __NV_E4M3);
    }
    *(uint2*)(g_x1q + (size_t)n * DIM + part * 8) = *(const uint2*)qv;

    pss[part][lane] = pos;
    __syncthreads();
    if (part == 0) {
        float pt = 0.f;
        #pragma unroll
        for (int p = 0; p < 8; p++) pt += pss[p][lane];
        g_pos[n] = pt;
    }
}

// ---------------------------------------------------------------------------
// Kernel B: negatives over the fp8 table. One warp per row; 8 groups of 4
// lanes each handle one k per iteration; lane loads uint4 (16 fp8 = 16B);
// full gathered row = 64B. This round: the 13 per-lane negative indices are
// PRELOADED INTO REGISTERS via coalesced global loads (no smem, no LDS on
// the critical path, no __syncwarp). Dot = 8 cvt + 8 HFMA2; 2-shuffle
// butterfly within the 4-lane group; per-row loss written to g_loss (no
// end-of-block sync — r6/r8 showed that costs more than it saves).
// ---------------------------------------------------------------------------
__global__ void __launch_bounds__(256) neg_kernel(const int* __restrict__ neg_idx) {
    int warp = threadIdx.x >> 5;
    int lane = threadIdx.x & 31;
    int n = blockIdx.x * 8 + warp;

    int grp = lane >> 2;  // which of 8 concurrent k's
    int sub = lane & 3;   // 16-dim chunk

    // Preload this lane's 13 indices (k = it*8 + grp, clamped) into registers.
    // At fixed it the warp reads a 32B span (8 ints, 4-way duplicated) -> one
    // sector per LDG; 13 independent LDGs issued up front.
    int jreg[13];
    const int* ip = neg_idx + (size_t)n * KNEG;
    #pragma unroll
    for (int it = 0; it < 13; it++) {
        int k = it * 8 + grp;
        jreg[it] = __ldg(ip + (k < KNEG ? k : KNEG - 1));
    }

    // query chunk: 16 fp8 -> 8 half2 in registers
    uint4 qraw = ((const uint4*)(g_x1q + (size_t)n * DIM))[sub];
    __half2 q[8];
    {
        const __nv_fp8x2_storage_t* qs = (const __nv_fp8x2_storage_t*)&qraw;
        #pragma unroll
        for (int i = 0; i < 8; i++) {
            __half2_raw hr = __nv_cvt_fp8x2_to_halfraw2(qs[i], __NV_E4M3);
            q[i] = *(__half2*)&hr;
        }
    }

    float negacc = 0.f;
    #pragma unroll
    for (int it = 0; it < 13; it++) {
        uint4 bv = ((const uint4*)(g_x1q + (size_t)jreg[it] * DIM))[sub];
        const __nv_fp8x2_storage_t* bs = (const __nv_fp8x2_storage_t*)&bv;
        __half2 acc = __floats2half2_rn(0.f, 0.f);
        #pragma unroll
        for (int i = 0; i < 8; i++) {
            __half2_raw hr = __nv_cvt_fp8x2_to_halfraw2(bs[i], __NV_E4M3);
            acc = __hfma2(q[i], *(__half2*)&hr, acc);
        }
        float2 f = __half22float2(acc);
        float p = f.x + f.y;
        p += __shfl_xor_sync(0xffffffffu, p, 2);
        p += __shfl_xor_sync(0xffffffffu, p, 1);
        float e = __expf(p);
        bool valid = (it * 8 + grp) < KNEG;
        negacc += valid ? e : 0.f;
    }
    negacc += __shfl_xor_sync(0xffffffffu, negacc, 4);
    negacc += __shfl_xor_sync(0xffffffffu, negacc, 8);
    negacc += __shfl_xor_sync(0xffffffffu, negacc, 16);

    if (lane == 0) {
        float pos = g_pos[n];
        g_loss[n] = logf(pos + negacc) - logf(pos);
    }
}

// ---------------------------------------------------------------------------
// Kernel C (round-4 proven): deterministic mean reduction, single block.
// ---------------------------------------------------------------------------
__global__ void reduce_kernel(float* __restrict__ out) {
    __shared__ float sb[1024];
    float s = 0.f;
    for (int i = threadIdx.x; i < NROWS; i += 1024) s += g_loss[i];
    sb[threadIdx.x] = s;
    __syncthreads();
    #pragma unroll
    for (int stride = 512; stride > 0; stride >>= 1) {
        if (threadIdx.x < stride) sb[threadIdx.x] += sb[threadIdx.x + stride];
        __syncthreads();
    }
    if (threadIdx.x == 0) out[0] = sb[0] / (float)NROWS;
}

extern "C" void kernel_launch(void* const* d_in, const int* in_sizes, int n_in,
                              void* d_out, int out_size) {
    const float* x1      = (const float*)d_in[0];
    const float* x2      = (const float*)d_in[1];
    const int*   neg_idx = (const int*)  d_in[2];
    float*       out     = (float*)d_out;

    normalize_kernel<<<NROWS / 32, 256>>>(x1, x2);
    neg_kernel<<<NROWS / 8, 256>>>(neg_idx);
    reduce_kernel<<<1, 1024>>>(out);
}

// round 10
// speedup vs baseline: 1.0011x; 1.0011x over previous
#include <cuda_runtime.h>
#include <cuda_fp16.h>
#include <cuda_fp8.h>
#include <math.h>

// Problem constants (fixed by the reference)
#define NROWS 25088     // B*H*W
#define DIM   64
#define KNEG  100
#define HW    3136      // H*W
#define DHW   200704    // D*H*W

// Scratch (no cudaMalloc allowed)
__device__ unsigned char g_x1q[NROWS * DIM];   // normalized x1, fp8 e4m3, 1.6MB
__device__ float         g_pos[NROWS];
__device__ float         g_loss[NROWS];

// ---------------------------------------------------------------------------
// Kernel A: normalization, 16 rows per 256-thread block (grid 1568 -> no
// grid starvation; regs allow 7 blocks/SM and we now offer 10.6).
// Thread t: row r = t & 15, dim chunk p = t >> 4 owns dims [4p, 4p+4).
// At fixed dim, each half-warp reads 16 consecutive hw -> 64B contiguous.
// Within a warp, chunks 2w and 2w+1 combine via shfl_xor(16); the 8 warp
// partials per row reduce through smem. 16 | 3136 -> no batch straddle.
// ---------------------------------------------------------------------------
__global__ void __launch_bounds__(256) normalize_kernel(const float* __restrict__ x1,
                                                        const float* __restrict__ x2) {
    __shared__ float s1s[8][16];
    __shared__ float s2s[8][16];
    __shared__ float pss[8][16];

    int t = threadIdx.x;
    int r = t & 15;                 // row within block
    int p = t >> 4;                 // dim chunk (4 dims)
    int w = t >> 5;                 // warp id
    int n = blockIdx.x * 16 + r;
    int b  = n / HW;
    int hw = n - b * HW;
    const float* p1 = x1 + (size_t)b * DHW + (size_t)(p * 4) * HW + hw;
    const float* p2 = x2 + (size_t)b * DHW + (size_t)(p * 4) * HW + hw;

    float v1[4], v2[4];
    #pragma unroll
    for (int i = 0; i < 4; i++) v1[i] = p1[i * HW];
    #pragma unroll
    for (int i = 0; i < 4; i++) v2[i] = p2[i * HW];

    float s1 = 0.f, s2 = 0.f;
    #pragma unroll
    for (int i = 0; i < 4; i++) {
        s1 = fmaf(v1[i], v1[i], s1);
        s2 = fmaf(v2[i], v2[i], s2);
    }
    // combine the two dim-chunks living in this warp (lane L <-> L^16, same row)
    s1 += __shfl_xor_sync(0xffffffffu, s1, 16);
    s2 += __shfl_xor_sync(0xffffffffu, s2, 16);
    if ((t & 31) < 16) { s1s[w][r] = s1; s2s[w][r] = s2; }
    __syncthreads();

    float t1 = 0.f, t2 = 0.f;
    #pragma unroll
    for (int q = 0; q < 8; q++) { t1 += s1s[q][r]; t2 += s2s[q][r]; }
    float sc1 = 1.0f / fmaxf(sqrtf(t1), 1e-12f);
    float sc2 = 1.0f / fmaxf(sqrtf(t2), 1e-12f);

    float pos = 0.f;
    __nv_fp8x2_storage_t qv[2];
    #pragma unroll
    for (int i = 0; i < 2; i++) {
        float a0 = v1[2*i]   * sc1;
        float a1 = v1[2*i+1] * sc1;
        pos += __expf(a0 * (v2[2*i]   * sc2));
        pos += __expf(a1 * (v2[2*i+1] * sc2));
        float2 f2; f2.x = a0; f2.y = a1;
        qv[i] = __nv_cvt_float2_to_fp8x2(f2, __NV_SATFINITE, __NV_E4M3);
    }
    *(unsigned int*)(g_x1q + (size_t)n * DIM + p * 4) = *(const unsigned int*)qv;

    pos += __shfl_xor_sync(0xffffffffu, pos, 16);
    if ((t & 31) < 16) pss[w][r] = pos;
    __syncthreads();
    if (t < 16) {
        float pt = 0.f;
        #pragma unroll
        for (int q = 0; q < 8; q++) pt += pss[q][r];
        g_pos[n] = pt;
    }
}

// ---------------------------------------------------------------------------
// Kernel B (byte-identical round-4 version): negatives over the fp8 table.
// One warp per row; 8 groups of 4 lanes each handle one k concurrently.
// Lane loads uint4 (16 fp8 = 16B); full gathered row = 64B. Dot = 8 cvt +
// 8 HFMA2; 2-shuffle butterfly within the 4-lane group; exp uniform.
// ---------------------------------------------------------------------------
__global__ void neg_kernel(const int* __restrict__ neg_idx) {
    __shared__ int sidx[8][KNEG];
    int warp = threadIdx.x >> 5;
    int lane = threadIdx.x & 31;
    int n = blockIdx.x * 8 + warp;

    for (int k = lane; k < KNEG; k += 32)
        sidx[warp][k] = neg_idx[(size_t)n * KNEG + k];
    __syncwarp();

    int grp = lane >> 2;  // which of 8 concurrent k's
    int sub = lane & 3;   // 16-dim chunk

    // query chunk: 16 fp8 -> 8 half2 in registers
    uint4 qraw = ((const uint4*)(g_x1q + (size_t)n * DIM))[sub];
    __half2 q[8];
    {
        const __nv_fp8x2_storage_t* qs = (const __nv_fp8x2_storage_t*)&qraw;
        #pragma unroll
        for (int i = 0; i < 8; i++) {
            __half2_raw hr = __nv_cvt_fp8x2_to_halfraw2(qs[i], __NV_E4M3);
            q[i] = *(__half2*)&hr;
        }
    }

    float negacc = 0.f;
    #pragma unroll
    for (int it = 0; it < 13; it++) {
        int k = it * 8 + grp;
        bool valid = (k < KNEG);
        int j = sidx[warp][valid ? k : (KNEG - 1)];
        uint4 bv = ((const uint4*)(g_x1q + (size_t)j * DIM))[sub];
        const __nv_fp8x2_storage_t* bs = (const __nv_fp8x2_storage_t*)&bv;
        __half2 acc = __floats2half2_rn(0.f, 0.f);
        #pragma unroll
        for (int i = 0; i < 8; i++) {
            __half2_raw hr = __nv_cvt_fp8x2_to_halfraw2(bs[i], __NV_E4M3);
            acc = __hfma2(q[i], *(__half2*)&hr, acc);
        }
        float2 f = __half22float2(acc);
        float p = f.x + f.y;
        p += __shfl_xor_sync(0xffffffffu, p, 2);
        p += __shfl_xor_sync(0xffffffffu, p, 1);
        float e = __expf(p);
        negacc += valid ? e : 0.f;
    }
    negacc += __shfl_xor_sync(0xffffffffu, negacc, 4);
    negacc += __shfl_xor_sync(0xffffffffu, negacc, 8);
    negacc += __shfl_xor_sync(0xffffffffu, negacc, 16);

    if (lane == 0) {
        float pos = g_pos[n];
        g_loss[n] = logf(pos + negacc) - logf(pos);
    }
}

// ---------------------------------------------------------------------------
// Kernel C (byte-identical round-4 version): deterministic mean reduction.
// ---------------------------------------------------------------------------
__global__ void reduce_kernel(float* __restrict__ out) {
    __shared__ float sb[1024];
    float s = 0.f;
    for (int i = threadIdx.x; i < NROWS; i += 1024) s += g_loss[i];
    sb[threadIdx.x] = s;
    __syncthreads();
    #pragma unroll
    for (int stride = 512; stride > 0; stride >>= 1) {
        if (threadIdx.x < stride) sb[threadIdx.x] += sb[threadIdx.x + stride];
        __syncthreads();
    }
    if (threadIdx.x == 0) out[0] = sb[0] / (float)NROWS;
}

extern "C" void kernel_launch(void* const* d_in, const int* in_sizes, int n_in,
                              void* d_out, int out_size) {
    const float* x1      = (const float*)d_in[0];
    const float* x2      = (const float*)d_in[1];
    const int*   neg_idx = (const int*)  d_in[2];
    float*       out     = (float*)d_out;

    normalize_kernel<<<NROWS / 16, 256>>>(x1, x2);
    neg_kernel<<<NROWS / 8, 256>>>(neg_idx);
    reduce_kernel<<<1, 1024>>>(out);
}